// round 1
// baseline (speedup 1.0000x reference)
#include <cuda_runtime.h>
#include <cstdint>

// Problem constants (fixed shapes for TopKGOATLayer_74156905333517)
#define T_TOK   8192
#define DMODEL  4096
#define N_EXP   8
#define RANK    64
#define ER      512   // N_EXP * RANK

// Scratch (no allocation allowed -> __device__ globals)
__device__ float g_w[T_TOK * N_EXP];   // dense routing weights (0 except top-2)
__device__ float g_H[T_TOK * ER];      // H = x @ A_all^T   (16 MB, L2-resident)

// ---------------------------------------------------------------------------
// helpers
// ---------------------------------------------------------------------------
__device__ __forceinline__ unsigned f2tf(float f) {
    unsigned r;
    asm("cvt.rna.tf32.f32 %0, %1;" : "=r"(r) : "f"(f));
    return r;
}

__device__ __forceinline__ void mma_tf32(float c[4], const unsigned a[4], const unsigned b[2]) {
    asm volatile(
        "mma.sync.aligned.m16n8k8.row.col.f32.tf32.tf32.f32 "
        "{%0,%1,%2,%3}, {%4,%5,%6,%7}, {%8,%9}, {%0,%1,%2,%3};\n"
        : "+f"(c[0]), "+f"(c[1]), "+f"(c[2]), "+f"(c[3])
        : "r"(a[0]), "r"(a[1]), "r"(a[2]), "r"(a[3]), "r"(b[0]), "r"(b[1]));
}

// ---------------------------------------------------------------------------
// Gate: logits = x @ gate_w^T ; top-2 + renormalize -> dense w[T,8]
// Block = 256 thr (8 warps), 64 tokens/block. Warp w owns tokens w*8..w*8+7.
// Lane = K-slice. Register tile: 8 tokens x 8 experts per lane.
// ---------------------------------------------------------------------------
__global__ __launch_bounds__(256) void gate_kernel(const float* __restrict__ x,
                                                   const float* __restrict__ gw,
                                                   float* __restrict__ wout)
{
    __shared__ float xs[64][68];
    __shared__ float gs[8][68];

    const int tid  = threadIdx.x;
    const int lane = tid & 31;
    const int warp = tid >> 5;
    const int tok0 = blockIdx.x * 64;

    float acc[8][8];
#pragma unroll
    for (int i = 0; i < 8; i++)
#pragma unroll
        for (int e = 0; e < 8; e++) acc[i][e] = 0.f;

    const int lr = tid >> 4;          // 0..15
    const int lc = (tid & 15) * 4;    // 0..60

    for (int kc = 0; kc < DMODEL; kc += 64) {
#pragma unroll
        for (int j = 0; j < 4; j++) {
            float4 v = *(const float4*)&x[(size_t)(tok0 + lr + j * 16) * DMODEL + kc + lc];
            *(float4*)&xs[lr + j * 16][lc] = v;
        }
        if (tid < 128) {
            int rr = tid >> 4;  // 0..7
            float4 v = *(const float4*)&gw[(size_t)rr * DMODEL + kc + lc];
            *(float4*)&gs[rr][lc] = v;
        }
        __syncthreads();

#pragma unroll
        for (int h = 0; h < 2; h++) {
            int kk = lane + h * 32;
            float gv[8];
#pragma unroll
            for (int e = 0; e < 8; e++) gv[e] = gs[e][kk];
#pragma unroll
            for (int i = 0; i < 8; i++) {
                float xv = xs[warp * 8 + i][kk];
#pragma unroll
                for (int e = 0; e < 8; e++) acc[i][e] += xv * gv[e];
            }
        }
        __syncthreads();
    }

    // butterfly reduce over the 32 k-slices
#pragma unroll
    for (int off = 16; off > 0; off >>= 1)
#pragma unroll
        for (int i = 0; i < 8; i++)
#pragma unroll
            for (int e = 0; e < 8; e++)
                acc[i][e] += __shfl_xor_sync(0xffffffffu, acc[i][e], off);

    // lane i handles token (warp*8 + i): top-2 + renorm (softmax denominators cancel)
#pragma unroll
    for (int i = 0; i < 8; i++) {
        if (lane == i) {
            float m1 = -1e30f; int e1 = 0;
#pragma unroll
            for (int e = 0; e < 8; e++)
                if (acc[i][e] > m1) { m1 = acc[i][e]; e1 = e; }
            float m2 = -1e30f; int e2 = 0;
#pragma unroll
            for (int e = 0; e < 8; e++)
                if (e != e1 && acc[i][e] > m2) { m2 = acc[i][e]; e2 = e; }
            float w1 = 1.0f / (1.0f + __expf(m2 - m1));
            int tok = tok0 + warp * 8 + i;
#pragma unroll
            for (int e = 0; e < 8; e++) wout[tok * 8 + e] = 0.f;
            wout[tok * 8 + e1] = w1;
            wout[tok * 8 + e2] = 1.0f - w1;
        }
    }
}

// ---------------------------------------------------------------------------
// Unified tf32 GEMM:  C[M,N] = A[M,K] * B[N,K]^T  (both K-contiguous)
// MODE 0: A = x (lda 4096), B = lora_A flat [512,4096], C = g_H (ldc 512)
// MODE 1: A = g_H scaled by w[t, k>>6] at SMEM-load time (lda 512),
//         B(n,k) = lora_B[e=(k>>6)][n][r=(k&63)], C = out (ldc 4096)
// Tiles: BM=BN=128, BK=32. 256 thr, warp grid 2x4, warp tile 64x32.
// grid.x = N-tiles (fastest -> N-siblings share A tile via L2), grid.y = M-tiles
// ---------------------------------------------------------------------------
template <int MODE>
__global__ __launch_bounds__(256) void gemm_tf32(const float* __restrict__ A,
                                                 const float* __restrict__ B,
                                                 const float* __restrict__ w8,
                                                 float* __restrict__ C)
{
    constexpr int K   = MODE ? ER : DMODEL;
    constexpr int LDA = MODE ? ER : DMODEL;
    constexpr int LDC = MODE ? DMODEL : ER;

    __shared__ float As[128][36];
    __shared__ float Bs[128][36];

    const int tid  = threadIdx.x;
    const int lane = tid & 31;
    const int warp = tid >> 5;
    const int wm   = warp >> 2;      // 0..1
    const int wn   = warp & 3;       // 0..3
    const int bn   = blockIdx.x * 128;
    const int bm   = blockIdx.y * 128;

    float c[4][4][4] = {};

    const int lr = tid >> 3;         // 0..31
    const int lc = (tid & 7) * 4;    // 0..28

    for (int k0 = 0; k0 < K; k0 += 32) {
        // ---- A tile (with routing-weight scale for MODE 1) ----
        float ws[4];
        if (MODE) {
            const int e = k0 >> 6;   // constant within BK=32 tile
#pragma unroll
            for (int j = 0; j < 4; j++)
                ws[j] = w8[(size_t)(bm + lr + j * 32) * N_EXP + e];
        }
#pragma unroll
        for (int j = 0; j < 4; j++) {
            int row = lr + j * 32;
            float4 v = *(const float4*)&A[(size_t)(bm + row) * LDA + k0 + lc];
            if (MODE) { v.x *= ws[j]; v.y *= ws[j]; v.z *= ws[j]; v.w *= ws[j]; }
            *(float4*)&As[row][lc] = v;
        }
        // ---- B tile ----
#pragma unroll
        for (int j = 0; j < 4; j++) {
            int n = lr + j * 32;
            const float* bp;
            if (MODE) {
                const int e  = k0 >> 6;
                const int r0 = k0 & 63;
                bp = &B[(size_t)e * DMODEL * RANK + (size_t)(bn + n) * RANK + r0 + lc];
            } else {
                bp = &B[(size_t)(bn + n) * DMODEL + k0 + lc];
            }
            *(float4*)&Bs[n][lc] = *(const float4*)bp;
        }
        __syncthreads();

        // ---- MMA over 4 k-steps of 8 ----
        const int r0 = lane >> 2;
        const int cq = lane & 3;
#pragma unroll
        for (int kk = 0; kk < 4; kk++) {
            const int k8 = kk * 8;
            unsigned a[4][4], b[4][2];
#pragma unroll
            for (int mi = 0; mi < 4; mi++) {
                int rb = wm * 64 + mi * 16 + r0;
                a[mi][0] = f2tf(As[rb][k8 + cq]);
                a[mi][1] = f2tf(As[rb + 8][k8 + cq]);
                a[mi][2] = f2tf(As[rb][k8 + cq + 4]);
                a[mi][3] = f2tf(As[rb + 8][k8 + cq + 4]);
            }
#pragma unroll
            for (int ni = 0; ni < 4; ni++) {
                int nb = wn * 32 + ni * 8 + r0;
                b[ni][0] = f2tf(Bs[nb][k8 + cq]);
                b[ni][1] = f2tf(Bs[nb][k8 + cq + 4]);
            }
#pragma unroll
            for (int mi = 0; mi < 4; mi++)
#pragma unroll
                for (int ni = 0; ni < 4; ni++)
                    mma_tf32(c[mi][ni], a[mi], b[ni]);
        }
        __syncthreads();
    }

    // ---- epilogue ----
    const int r0 = lane >> 2;
    const int cq = lane & 3;
#pragma unroll
    for (int mi = 0; mi < 4; mi++) {
#pragma unroll
        for (int ni = 0; ni < 4; ni++) {
            int row = bm + wm * 64 + mi * 16 + r0;
            int col = bn + wn * 32 + ni * 8 + cq * 2;
            *(float2*)&C[(size_t)row * LDC + col]       = make_float2(c[mi][ni][0], c[mi][ni][1]);
            *(float2*)&C[(size_t)(row + 8) * LDC + col] = make_float2(c[mi][ni][2], c[mi][ni][3]);
        }
    }
}

// ---------------------------------------------------------------------------
// launch
// ---------------------------------------------------------------------------
extern "C" void kernel_launch(void* const* d_in, const int* in_sizes, int n_in,
                              void* d_out, int out_size)
{
    const float* x  = (const float*)d_in[0];   // [4,2048,4096]
    const float* gw = (const float*)d_in[1];   // [8,4096]
    const float* lA = (const float*)d_in[2];   // [8,64,4096]  == [512,4096]
    const float* lB = (const float*)d_in[3];   // [8,4096,64]
    float* out = (float*)d_out;                // [4,2048,4096]

    float* wp; float* Hp;
    cudaGetSymbolAddress((void**)&wp, g_w);
    cudaGetSymbolAddress((void**)&Hp, g_H);

    // 1) gate -> dense top-2 weights
    gate_kernel<<<T_TOK / 64, 256>>>(x, gw, wp);
    // 2) H = x @ A_all^T   (grid: N fastest for L2 reuse of x tiles)
    gemm_tf32<0><<<dim3(ER / 128, T_TOK / 128), 256>>>(x, lA, nullptr, Hp);
    // 3) out = (w .* H) @ B_cat
    gemm_tf32<1><<<dim3(DMODEL / 128, T_TOK / 128), 256>>>(Hp, lB, wp, out);
}

// round 2
// speedup vs baseline: 1.0983x; 1.0983x over previous
#include <cuda_runtime.h>
#include <cstdint>

// Fixed shapes for TopKGOATLayer_74156905333517
#define T_TOK   8192
#define DMODEL  4096
#define N_EXP   8
#define RANK    64
#define ER      512   // N_EXP * RANK
#define KSPLIT  4

// Scratch (no allocation allowed -> __device__ globals)
__device__ float g_w[T_TOK * N_EXP];            // dense routing weights
__device__ float g_H[T_TOK * ER];               // Hw = (x @ A_all^T) * w  (16 MB)
__device__ float g_lp[KSPLIT * T_TOK * N_EXP];  // gate logit partials

// ---------------------------------------------------------------------------
// helpers
// ---------------------------------------------------------------------------
__device__ __forceinline__ unsigned f2tf(float f) {
    unsigned r;
    asm("cvt.rna.tf32.f32 %0, %1;" : "=r"(r) : "f"(f));
    return r;
}

__device__ __forceinline__ void mma_tf32(float c[4], const unsigned a[4], const unsigned b[2]) {
    asm volatile(
        "mma.sync.aligned.m16n8k8.row.col.f32.tf32.tf32.f32 "
        "{%0,%1,%2,%3}, {%4,%5,%6,%7}, {%8,%9}, {%0,%1,%2,%3};\n"
        : "+f"(c[0]), "+f"(c[1]), "+f"(c[2]), "+f"(c[3])
        : "r"(a[0]), "r"(a[1]), "r"(a[2]), "r"(a[3]), "r"(b[0]), "r"(b[1]));
}

__device__ __forceinline__ void cp_async16(uint32_t saddr, const void* gaddr) {
    asm volatile("cp.async.cg.shared.global [%0], [%1], 16;\n" :: "r"(saddr), "l"(gaddr));
}
__device__ __forceinline__ void cp_commit() { asm volatile("cp.async.commit_group;\n"); }
template <int N> __device__ __forceinline__ void cp_wait() {
    asm volatile("cp.async.wait_group %0;\n" :: "n"(N));
}

// ---------------------------------------------------------------------------
// Gate partials: logits[t,e] over k-chunk of 1024.  grid = (128, 4), 256 thr.
// Warp w owns tokens w*8..w*8+7; lane = k-slice; 8 tok x 8 exp register tile.
// ---------------------------------------------------------------------------
__global__ __launch_bounds__(256) void gate_part(const float* __restrict__ x,
                                                 const float* __restrict__ gw,
                                                 float* __restrict__ lp)
{
    __shared__ float xs[64][68];
    __shared__ float gs[8][68];

    const int tid  = threadIdx.x;
    const int lane = tid & 31;
    const int warp = tid >> 5;
    const int tok0 = blockIdx.x * 64;
    const int kc0  = blockIdx.y * (DMODEL / KSPLIT);

    float acc[8][8];
#pragma unroll
    for (int i = 0; i < 8; i++)
#pragma unroll
        for (int e = 0; e < 8; e++) acc[i][e] = 0.f;

    const int lr = tid >> 4;          // 0..15
    const int lc = (tid & 15) * 4;    // 0..60

    for (int kc = kc0; kc < kc0 + DMODEL / KSPLIT; kc += 64) {
#pragma unroll
        for (int j = 0; j < 4; j++) {
            float4 v = *(const float4*)&x[(size_t)(tok0 + lr + j * 16) * DMODEL + kc + lc];
            *(float4*)&xs[lr + j * 16][lc] = v;
        }
        if (tid < 128) {
            int rr = tid >> 4;
            float4 v = *(const float4*)&gw[(size_t)rr * DMODEL + kc + lc];
            *(float4*)&gs[rr][lc] = v;
        }
        __syncthreads();

#pragma unroll
        for (int h = 0; h < 2; h++) {
            int kk = lane + h * 32;
            float gv[8];
#pragma unroll
            for (int e = 0; e < 8; e++) gv[e] = gs[e][kk];
#pragma unroll
            for (int i = 0; i < 8; i++) {
                float xv = xs[warp * 8 + i][kk];
#pragma unroll
                for (int e = 0; e < 8; e++) acc[i][e] += xv * gv[e];
            }
        }
        __syncthreads();
    }

#pragma unroll
    for (int off = 16; off > 0; off >>= 1)
#pragma unroll
        for (int i = 0; i < 8; i++)
#pragma unroll
            for (int e = 0; e < 8; e++)
                acc[i][e] += __shfl_xor_sync(0xffffffffu, acc[i][e], off);

#pragma unroll
    for (int i = 0; i < 8; i++) {
        if (lane == i) {
            int tok = tok0 + warp * 8 + i;
            size_t base = ((size_t)blockIdx.y * T_TOK + tok) * N_EXP;
#pragma unroll
            for (int e = 0; e < 8; e++) lp[base + e] = acc[i][e];
        }
    }
}

// ---------------------------------------------------------------------------
// Gate finalize: sum partials, top-2 + renorm -> dense w[T,8]
// ---------------------------------------------------------------------------
__global__ __launch_bounds__(256) void gate_fin(const float* __restrict__ lp,
                                                float* __restrict__ wout)
{
    const int tok = blockIdx.x * 256 + threadIdx.x;
    float l[8];
#pragma unroll
    for (int e = 0; e < 8; e++) l[e] = 0.f;
#pragma unroll
    for (int s = 0; s < KSPLIT; s++) {
        size_t base = ((size_t)s * T_TOK + tok) * N_EXP;
#pragma unroll
        for (int e = 0; e < 8; e++) l[e] += lp[base + e];
    }
    float m1 = -1e30f; int e1 = 0;
#pragma unroll
    for (int e = 0; e < 8; e++)
        if (l[e] > m1) { m1 = l[e]; e1 = e; }
    float m2 = -1e30f; int e2 = 0;
#pragma unroll
    for (int e = 0; e < 8; e++)
        if (e != e1 && l[e] > m2) { m2 = l[e]; e2 = e; }
    float w1 = 1.0f / (1.0f + __expf(m2 - m1));
#pragma unroll
    for (int e = 0; e < 8; e++) wout[tok * 8 + e] = 0.f;
    wout[tok * 8 + e1] = w1;
    wout[tok * 8 + e2] = 1.0f - w1;
}

// ---------------------------------------------------------------------------
// tf32 GEMM with 3-stage cp.async pipeline:  C[M,N] = A[M,K] * B[N,K]^T
// MODE 0: A = x (lda 4096), B = lora_A [512,4096], C = g_H (ldc 512),
//         epilogue scales by w[row, col>>6]   (Hw = (x A^T) .* w)
// MODE 1: A = g_H=Hw (lda 512), B(n,k) = lora_B[k>>6][n][k&63], C = out (4096)
// Tiles: BM=BN=128, BK=32. 256 thr, warp grid 2x4, warp tile 64x32.
// ---------------------------------------------------------------------------
#define PAD   36
#define TILEF (128 * PAD)          // floats per operand tile
#define SMEM_BYTES (3 * 2 * TILEF * 4)

template <int MODE>
__global__ __launch_bounds__(256) void gemm_tf32(const float* __restrict__ A,
                                                 const float* __restrict__ B,
                                                 const float* __restrict__ w8,
                                                 float* __restrict__ C)
{
    constexpr int K   = MODE ? ER : DMODEL;
    constexpr int LDA = MODE ? ER : DMODEL;
    constexpr int LDC = MODE ? DMODEL : ER;
    constexpr int KT  = K / 32;

    extern __shared__ float sm[];

    const int tid  = threadIdx.x;
    const int lane = tid & 31;
    const int warp = tid >> 5;
    const int wm   = warp >> 2;
    const int wn   = warp & 3;
    const int bn   = blockIdx.x * 128;
    const int bm   = blockIdx.y * 128;
    const int lr   = tid >> 3;        // 0..31
    const int lc   = (tid & 7) * 4;   // 0..28

    const uint32_t smbase = (uint32_t)__cvta_generic_to_shared(sm);

    auto issue = [&](int kt, int s) {
        const int k0 = kt * 32;
        const uint32_t sa = smbase + (uint32_t)(s * 2 * TILEF) * 4u;
        const uint32_t sb = sa + TILEF * 4u;
#pragma unroll
        for (int j = 0; j < 4; j++) {
            int row = lr + j * 32;
            cp_async16(sa + (row * PAD + lc) * 4u,
                       &A[(size_t)(bm + row) * LDA + k0 + lc]);
        }
#pragma unroll
        for (int j = 0; j < 4; j++) {
            int n = lr + j * 32;
            const float* bp;
            if (MODE) {
                const int e  = k0 >> 6;
                const int r0 = k0 & 63;
                bp = &B[(size_t)e * DMODEL * RANK + (size_t)(bn + n) * RANK + r0 + lc];
            } else {
                bp = &B[(size_t)(bn + n) * DMODEL + k0 + lc];
            }
            cp_async16(sb + (n * PAD + lc) * 4u, bp);
        }
    };

    float c[4][4][4] = {};

    issue(0, 0); cp_commit();
    issue(1, 1); cp_commit();

    const int r0 = lane >> 2;
    const int cq = lane & 3;

    for (int kt = 0; kt < KT; kt++) {
        cp_wait<1>();
        __syncthreads();

        // prefetch next stage into the buffer freed by the barrier above
        if (kt + 2 < KT) issue(kt + 2, (kt + 2) % 3);
        cp_commit();

        const float* As = sm + (kt % 3) * 2 * TILEF;
        const float* Bs = As + TILEF;

#pragma unroll
        for (int kk = 0; kk < 4; kk++) {
            const int k8 = kk * 8;
            unsigned a[4][4], b[4][2];
#pragma unroll
            for (int mi = 0; mi < 4; mi++) {
                int rb = wm * 64 + mi * 16 + r0;
                a[mi][0] = f2tf(As[rb * PAD + k8 + cq]);
                a[mi][1] = f2tf(As[(rb + 8) * PAD + k8 + cq]);
                a[mi][2] = f2tf(As[rb * PAD + k8 + cq + 4]);
                a[mi][3] = f2tf(As[(rb + 8) * PAD + k8 + cq + 4]);
            }
#pragma unroll
            for (int ni = 0; ni < 4; ni++) {
                int nb = wn * 32 + ni * 8 + r0;
                b[ni][0] = f2tf(Bs[nb * PAD + k8 + cq]);
                b[ni][1] = f2tf(Bs[nb * PAD + k8 + cq + 4]);
            }
#pragma unroll
            for (int mi = 0; mi < 4; mi++)
#pragma unroll
                for (int ni = 0; ni < 4; ni++)
                    mma_tf32(c[mi][ni], a[mi], b[ni]);
        }
        __syncthreads();
    }

    // ---- epilogue ----
#pragma unroll
    for (int mi = 0; mi < 4; mi++) {
#pragma unroll
        for (int ni = 0; ni < 4; ni++) {
            int row = bm + wm * 64 + mi * 16 + r0;
            int col = bn + wn * 32 + ni * 8 + cq * 2;
            float s0 = 1.f, s1 = 1.f;
            if (MODE == 0) {
                int e = col >> 6;   // expert of this H column
                s0 = w8[(size_t)row * N_EXP + e];
                s1 = w8[(size_t)(row + 8) * N_EXP + e];
            }
            *(float2*)&C[(size_t)row * LDC + col] =
                make_float2(c[mi][ni][0] * s0, c[mi][ni][1] * s0);
            *(float2*)&C[(size_t)(row + 8) * LDC + col] =
                make_float2(c[mi][ni][2] * s1, c[mi][ni][3] * s1);
        }
    }
}

// ---------------------------------------------------------------------------
// launch
// ---------------------------------------------------------------------------
extern "C" void kernel_launch(void* const* d_in, const int* in_sizes, int n_in,
                              void* d_out, int out_size)
{
    const float* x  = (const float*)d_in[0];   // [4,2048,4096]
    const float* gw = (const float*)d_in[1];   // [8,4096]
    const float* lA = (const float*)d_in[2];   // [8,64,4096] == [512,4096]
    const float* lB = (const float*)d_in[3];   // [8,4096,64]
    float* out = (float*)d_out;                // [4,2048,4096]

    float* wp; float* Hp; float* lpp;
    cudaGetSymbolAddress((void**)&wp,  g_w);
    cudaGetSymbolAddress((void**)&Hp,  g_H);
    cudaGetSymbolAddress((void**)&lpp, g_lp);

    cudaFuncSetAttribute((const void*)gemm_tf32<0>,
                         cudaFuncAttributeMaxDynamicSharedMemorySize, SMEM_BYTES);
    cudaFuncSetAttribute((const void*)gemm_tf32<1>,
                         cudaFuncAttributeMaxDynamicSharedMemorySize, SMEM_BYTES);

    // 1) gate partial logits (K-split x4 for full-chip occupancy)
    gate_part<<<dim3(T_TOK / 64, KSPLIT), 256>>>(x, gw, lpp);
    // 2) finalize: top-2 + renorm -> dense w
    gate_fin<<<T_TOK / 256, 256>>>(lpp, wp);
    // 3) Hw = (x @ A_all^T) .* w   (w folded into epilogue)
    gemm_tf32<0><<<dim3(ER / 128, T_TOK / 128), 256, SMEM_BYTES>>>(x, lA, wp, Hp);
    // 4) out = Hw @ B_cat
    gemm_tf32<1><<<dim3(DMODEL / 128, T_TOK / 128), 256, SMEM_BYTES>>>(Hp, lB, nullptr, out);
}

// round 4
// speedup vs baseline: 1.2175x; 1.1085x over previous
#include <cuda_runtime.h>
#include <cstdint>

// Fixed shapes for TopKGOATLayer_74156905333517
#define T_TOK   8192
#define DMODEL  4096
#define N_EXP   8
#define RANK    64
#define ER      512
#define KSPLIT  4

// Scratch (no allocation allowed -> __device__ globals)
__device__ __align__(16) float g_xr[T_TOK * DMODEL];        // tf32-rounded x
__device__ __align__(16) float g_Ar[ER * DMODEL];           // tf32-rounded lora_A
__device__ __align__(16) float g_Br[N_EXP * DMODEL * RANK]; // tf32-rounded lora_B
__device__ __align__(16) float g_H[T_TOK * ER];             // Hw (scaled, tf32-rounded)
__device__ float g_w[T_TOK * N_EXP];
__device__ float g_lp[KSPLIT * T_TOK * N_EXP];

// ---------------------------------------------------------------------------
// helpers
// ---------------------------------------------------------------------------
__device__ __forceinline__ unsigned f2tf(float f) {
    unsigned r;
    asm("cvt.rna.tf32.f32 %0, %1;" : "=r"(r) : "f"(f));
    return r;
}

__device__ __forceinline__ void mma_tf32(float c[4], const unsigned a[4], const unsigned b[2]) {
    asm volatile(
        "mma.sync.aligned.m16n8k8.row.col.f32.tf32.tf32.f32 "
        "{%0,%1,%2,%3}, {%4,%5,%6,%7}, {%8,%9}, {%0,%1,%2,%3};\n"
        : "+f"(c[0]), "+f"(c[1]), "+f"(c[2]), "+f"(c[3])
        : "r"(a[0]), "r"(a[1]), "r"(a[2]), "r"(a[3]), "r"(b[0]), "r"(b[1]));
}

__device__ __forceinline__ void cp_async16(uint32_t saddr, const void* gaddr) {
    asm volatile("cp.async.cg.shared.global [%0], [%1], 16;\n" :: "r"(saddr), "l"(gaddr));
}
__device__ __forceinline__ void cp_commit() { asm volatile("cp.async.commit_group;\n"); }
template <int N> __device__ __forceinline__ void cp_wait() {
    asm volatile("cp.async.wait_group %0;\n" :: "n"(N));
}

// ---------------------------------------------------------------------------
// tf32 pre-rounding (weights only; x rounding fused into gate_part)
// ---------------------------------------------------------------------------
__global__ __launch_bounds__(256) void round_tf32(const float4* __restrict__ src,
                                                  float4* __restrict__ dst, int n4)
{
    int i = blockIdx.x * 256 + threadIdx.x;
    if (i < n4) {
        float4 v = src[i];
        v.x = __uint_as_float(f2tf(v.x));
        v.y = __uint_as_float(f2tf(v.y));
        v.z = __uint_as_float(f2tf(v.z));
        v.w = __uint_as_float(f2tf(v.w));
        dst[i] = v;
    }
}

// ---------------------------------------------------------------------------
// Gate partials + fused x->tf32 rounding.  grid = (T/64, KSPLIT), 256 thr.
// Each (t,k) element of x is touched by exactly one block -> write rounded copy.
// ---------------------------------------------------------------------------
__global__ __launch_bounds__(256) void gate_part(const float* __restrict__ x,
                                                 const float* __restrict__ gw,
                                                 float* __restrict__ lp,
                                                 float* __restrict__ xr)
{
    __shared__ float xs[64][68];
    __shared__ float gs[8][68];

    const int tid  = threadIdx.x;
    const int lane = tid & 31;
    const int warp = tid >> 5;
    const int tok0 = blockIdx.x * 64;
    const int kc0  = blockIdx.y * (DMODEL / KSPLIT);

    float acc[8][8];
#pragma unroll
    for (int i = 0; i < 8; i++)
#pragma unroll
        for (int e = 0; e < 8; e++) acc[i][e] = 0.f;

    const int lr = tid >> 4;
    const int lc = (tid & 15) * 4;

    for (int kc = kc0; kc < kc0 + DMODEL / KSPLIT; kc += 64) {
#pragma unroll
        for (int j = 0; j < 4; j++) {
            size_t gi = (size_t)(tok0 + lr + j * 16) * DMODEL + kc + lc;
            float4 v = *(const float4*)&x[gi];
            *(float4*)&xs[lr + j * 16][lc] = v;
            float4 r;
            r.x = __uint_as_float(f2tf(v.x));
            r.y = __uint_as_float(f2tf(v.y));
            r.z = __uint_as_float(f2tf(v.z));
            r.w = __uint_as_float(f2tf(v.w));
            *(float4*)&xr[gi] = r;
        }
        if (tid < 128) {
            int rr = tid >> 4;
            float4 v = *(const float4*)&gw[(size_t)rr * DMODEL + kc + lc];
            *(float4*)&gs[rr][lc] = v;
        }
        __syncthreads();

#pragma unroll
        for (int h = 0; h < 2; h++) {
            int kk = lane + h * 32;
            float gv[8];
#pragma unroll
            for (int e = 0; e < 8; e++) gv[e] = gs[e][kk];
#pragma unroll
            for (int i = 0; i < 8; i++) {
                float xv = xs[warp * 8 + i][kk];
#pragma unroll
                for (int e = 0; e < 8; e++) acc[i][e] += xv * gv[e];
            }
        }
        __syncthreads();
    }

#pragma unroll
    for (int off = 16; off > 0; off >>= 1)
#pragma unroll
        for (int i = 0; i < 8; i++)
#pragma unroll
            for (int e = 0; e < 8; e++)
                acc[i][e] += __shfl_xor_sync(0xffffffffu, acc[i][e], off);

#pragma unroll
    for (int i = 0; i < 8; i++) {
        if (lane == i) {
            int tok = tok0 + warp * 8 + i;
            size_t base = ((size_t)blockIdx.y * T_TOK + tok) * N_EXP;
#pragma unroll
            for (int e = 0; e < 8; e++) lp[base + e] = acc[i][e];
        }
    }
}

__global__ __launch_bounds__(256) void gate_fin(const float* __restrict__ lp,
                                                float* __restrict__ wout)
{
    const int tok = blockIdx.x * 256 + threadIdx.x;
    float l[8];
#pragma unroll
    for (int e = 0; e < 8; e++) l[e] = 0.f;
#pragma unroll
    for (int s = 0; s < KSPLIT; s++) {
        size_t base = ((size_t)s * T_TOK + tok) * N_EXP;
#pragma unroll
        for (int e = 0; e < 8; e++) l[e] += lp[base + e];
    }
    float m1 = -1e30f; int e1 = 0;
#pragma unroll
    for (int e = 0; e < 8; e++)
        if (l[e] > m1) { m1 = l[e]; e1 = e; }
    float m2 = -1e30f; int e2 = 0;
#pragma unroll
    for (int e = 0; e < 8; e++)
        if (e != e1 && l[e] > m2) { m2 = l[e]; e2 = e; }
    float w1 = 1.0f / (1.0f + __expf(m2 - m1));
#pragma unroll
    for (int e = 0; e < 8; e++) wout[tok * 8 + e] = 0.f;
    wout[tok * 8 + e1] = w1;
    wout[tok * 8 + e2] = 1.0f - w1;
}

// ---------------------------------------------------------------------------
// tf32 GEMM, 2-stage cp.async, pre-rounded operands (NO cvt in mainloop).
// C[M,N] = A[M,K] * B[N,K]^T
// MODE 0: A = g_xr (lda 4096), B = g_Ar [512,4096], C = g_H
//         (epilogue: * w[row, col>>6], tf32-round)
// MODE 1: A = g_H (lda 512), B(n,k) = g_Br[k>>6][n][k&63], C = out (4096)
// BM=BN=128, BK=32. 256 thr, warps 2x4, warp tile 64x32. 2 CTAs/SM.
// ---------------------------------------------------------------------------
#define PAD   36
#define TILEF (128 * PAD)
#define SMEM_BYTES (2 * 2 * TILEF * 4)   // 2 stages x (As+Bs) = 73.7 KB

template <int MODE>
__global__ __launch_bounds__(256, 2) void gemm_tf32(const float* __restrict__ A,
                                                    const float* __restrict__ B,
                                                    const float* __restrict__ w8,
                                                    float* __restrict__ C)
{
    constexpr int K   = MODE ? ER : DMODEL;
    constexpr int LDA = MODE ? ER : DMODEL;
    constexpr int LDC = MODE ? DMODEL : ER;
    constexpr int KT  = K / 32;

    extern __shared__ float sm[];

    const int tid  = threadIdx.x;
    const int lane = tid & 31;
    const int warp = tid >> 5;
    const int wm   = warp >> 2;
    const int wn   = warp & 3;
    const int bn   = blockIdx.x * 128;
    const int bm   = blockIdx.y * 128;
    const int lr   = tid >> 3;        // 0..31
    const int lc   = (tid & 7) * 4;   // 0..28

    const uint32_t smbase = (uint32_t)__cvta_generic_to_shared(sm);

    auto issue = [&](int kt) {
        const int s  = kt & 1;
        const int k0 = kt * 32;
        const uint32_t sa = smbase + (uint32_t)(s * 2 * TILEF) * 4u;
        const uint32_t sb = sa + TILEF * 4u;
#pragma unroll
        for (int j = 0; j < 4; j++) {
            int row = lr + j * 32;
            cp_async16(sa + (row * PAD + lc) * 4u,
                       &A[(size_t)(bm + row) * LDA + k0 + lc]);
        }
#pragma unroll
        for (int j = 0; j < 4; j++) {
            int n = lr + j * 32;
            const float* bp;
            if (MODE) {
                const int e  = k0 >> 6;
                const int r0 = k0 & 63;
                bp = &B[(size_t)e * DMODEL * RANK + (size_t)(bn + n) * RANK + r0 + lc];
            } else {
                bp = &B[(size_t)(bn + n) * DMODEL + k0 + lc];
            }
            cp_async16(sb + (n * PAD + lc) * 4u, bp);
        }
    };

    float c[4][4][4] = {};

    issue(0); cp_commit();

    const int r0 = lane >> 2;
    const int cq = lane & 3;

    for (int kt = 0; kt < KT; kt++) {
        if (kt + 1 < KT) { issue(kt + 1); cp_commit(); cp_wait<1>(); }
        else             { cp_wait<0>(); }
        __syncthreads();

        const float* As = sm + (kt & 1) * 2 * TILEF;
        const float* Bs = As + TILEF;

#pragma unroll
        for (int kk = 0; kk < 4; kk++) {
            const int k8 = kk * 8;
            unsigned a[4][4], b[4][2];
#pragma unroll
            for (int mi = 0; mi < 4; mi++) {
                int rb = wm * 64 + mi * 16 + r0;
                a[mi][0] = __float_as_uint(As[rb * PAD + k8 + cq]);
                a[mi][1] = __float_as_uint(As[(rb + 8) * PAD + k8 + cq]);
                a[mi][2] = __float_as_uint(As[rb * PAD + k8 + cq + 4]);
                a[mi][3] = __float_as_uint(As[(rb + 8) * PAD + k8 + cq + 4]);
            }
#pragma unroll
            for (int ni = 0; ni < 4; ni++) {
                int nb = wn * 32 + ni * 8 + r0;
                b[ni][0] = __float_as_uint(Bs[nb * PAD + k8 + cq]);
                b[ni][1] = __float_as_uint(Bs[nb * PAD + k8 + cq + 4]);
            }
#pragma unroll
            for (int mi = 0; mi < 4; mi++)
#pragma unroll
                for (int ni = 0; ni < 4; ni++)
                    mma_tf32(c[mi][ni], a[mi], b[ni]);
        }
        __syncthreads();
    }

    // ---- epilogue (MODE 0: scale by routing weight + tf32-round Hw) ----
#pragma unroll
    for (int mi = 0; mi < 4; mi++) {
#pragma unroll
        for (int ni = 0; ni < 4; ni++) {
            int row = bm + wm * 64 + mi * 16 + r0;
            int col = bn + wn * 32 + ni * 8 + cq * 2;
            float v0 = c[mi][ni][0], v1 = c[mi][ni][1];
            float v2 = c[mi][ni][2], v3 = c[mi][ni][3];
            if (MODE == 0) {
                int e = col >> 6;
                float s0 = w8[(size_t)row * N_EXP + e];
                float s1 = w8[(size_t)(row + 8) * N_EXP + e];
                v0 = __uint_as_float(f2tf(v0 * s0));
                v1 = __uint_as_float(f2tf(v1 * s0));
                v2 = __uint_as_float(f2tf(v2 * s1));
                v3 = __uint_as_float(f2tf(v3 * s1));
            }
            *(float2*)&C[(size_t)row * LDC + col]       = make_float2(v0, v1);
            *(float2*)&C[(size_t)(row + 8) * LDC + col] = make_float2(v2, v3);
        }
    }
}

// ---------------------------------------------------------------------------
// launch
// ---------------------------------------------------------------------------
extern "C" void kernel_launch(void* const* d_in, const int* in_sizes, int n_in,
                              void* d_out, int out_size)
{
    const float* x  = (const float*)d_in[0];   // [4,2048,4096]
    const float* gw = (const float*)d_in[1];   // [8,4096]
    const float* lA = (const float*)d_in[2];   // [8,64,4096] == [512,4096]
    const float* lB = (const float*)d_in[3];   // [8,4096,64]
    float* out = (float*)d_out;

    float *wp, *Hp, *lpp, *xr, *Ar, *Br;
    cudaGetSymbolAddress((void**)&wp,  g_w);
    cudaGetSymbolAddress((void**)&Hp,  g_H);
    cudaGetSymbolAddress((void**)&lpp, g_lp);
    cudaGetSymbolAddress((void**)&xr,  g_xr);
    cudaGetSymbolAddress((void**)&Ar,  g_Ar);
    cudaGetSymbolAddress((void**)&Br,  g_Br);

    cudaFuncSetAttribute((const void*)gemm_tf32<0>,
                         cudaFuncAttributeMaxDynamicSharedMemorySize, SMEM_BYTES);
    cudaFuncSetAttribute((const void*)gemm_tf32<1>,
                         cudaFuncAttributeMaxDynamicSharedMemorySize, SMEM_BYTES);

    // 1) round LoRA weights to tf32 (small)
    round_tf32<<<(ER * DMODEL / 4 + 255) / 256, 256>>>((const float4*)lA, (float4*)Ar, ER * DMODEL / 4);
    round_tf32<<<(ER * DMODEL / 4 + 255) / 256, 256>>>((const float4*)lB, (float4*)Br, ER * DMODEL / 4);
    // 2) gate partials (fused x->tf32 rounding) + finalize
    gate_part<<<dim3(T_TOK / 64, KSPLIT), 256>>>(x, gw, lpp, xr);
    gate_fin<<<T_TOK / 256, 256>>>(lpp, wp);
    // 3) Hw = (x @ A_all^T) .* w  (scale + round in epilogue)
    gemm_tf32<0><<<dim3(ER / 128, T_TOK / 128), 256, SMEM_BYTES>>>(xr, Ar, wp, Hp);
    // 4) out = Hw @ B_cat
    gemm_tf32<1><<<dim3(DMODEL / 128, T_TOK / 128), 256, SMEM_BYTES>>>(Hp, Br, nullptr, out);
}

// round 5
// speedup vs baseline: 1.6162x; 1.3275x over previous
#include <cuda_runtime.h>
#include <cstdint>

// Fixed shapes for TopKGOATLayer_74156905333517
#define T_TOK   8192
#define DMODEL  4096
#define N_EXP   8
#define RANK    64
#define ER      512
#define KSPLIT  4
#define MAXTIL  64          // worst-case M-tiles per expert (8192/128)

// Scratch (__device__ globals; zero-initialized at load)
__device__ __align__(16) float g_xr[T_TOK * DMODEL];        // tf32-rounded x
__device__ __align__(16) float g_Ar[ER * DMODEL];           // tf32-rounded lora_A
__device__ __align__(16) float g_Br[N_EXP * DMODEL * RANK]; // tf32-rounded lora_B
__device__ __align__(16) float g_H[N_EXP * T_TOK * RANK];   // compact Hw per expert
__device__ float g_lp[KSPLIT * T_TOK * N_EXP];
__device__ int   g_cnt[N_EXP];
__device__ int   g_list[N_EXP * T_TOK];
__device__ float g_wl[N_EXP * T_TOK];

// ---------------------------------------------------------------------------
// helpers
// ---------------------------------------------------------------------------
__device__ __forceinline__ unsigned f2tf(float f) {
    unsigned r;
    asm("cvt.rna.tf32.f32 %0, %1;" : "=r"(r) : "f"(f));
    return r;
}

__device__ __forceinline__ void mma_tf32(float c[4], const unsigned a[4], const unsigned b[2]) {
    asm volatile(
        "mma.sync.aligned.m16n8k8.row.col.f32.tf32.tf32.f32 "
        "{%0,%1,%2,%3}, {%4,%5,%6,%7}, {%8,%9}, {%0,%1,%2,%3};\n"
        : "+f"(c[0]), "+f"(c[1]), "+f"(c[2]), "+f"(c[3])
        : "r"(a[0]), "r"(a[1]), "r"(a[2]), "r"(a[3]), "r"(b[0]), "r"(b[1]));
}

__device__ __forceinline__ void cp_async16(uint32_t saddr, const void* gaddr) {
    asm volatile("cp.async.cg.shared.global [%0], [%1], 16;\n" :: "r"(saddr), "l"(gaddr));
}
__device__ __forceinline__ void cp_commit() { asm volatile("cp.async.commit_group;\n"); }
template <int N> __device__ __forceinline__ void cp_wait() {
    asm volatile("cp.async.wait_group %0;\n" :: "n"(N));
}

// ---------------------------------------------------------------------------
// tf32 pre-rounding (LoRA weights)
// ---------------------------------------------------------------------------
__global__ __launch_bounds__(256) void round_tf32(const float4* __restrict__ src,
                                                  float4* __restrict__ dst, int n4)
{
    int i = blockIdx.x * 256 + threadIdx.x;
    if (i < n4) {
        float4 v = src[i];
        v.x = __uint_as_float(f2tf(v.x));
        v.y = __uint_as_float(f2tf(v.y));
        v.z = __uint_as_float(f2tf(v.z));
        v.w = __uint_as_float(f2tf(v.w));
        dst[i] = v;
    }
}

// ---------------------------------------------------------------------------
// zero out[] and expert counters (graph-safe, no cudaMemset)
// ---------------------------------------------------------------------------
__global__ __launch_bounds__(256) void zero_out(float4* __restrict__ out, int n4,
                                                int* __restrict__ cnt)
{
    int i = blockIdx.x * 256 + threadIdx.x;
    if (i < n4) out[i] = make_float4(0.f, 0.f, 0.f, 0.f);
    if (blockIdx.x == 0 && threadIdx.x < N_EXP) cnt[threadIdx.x] = 0;
}

// ---------------------------------------------------------------------------
// Gate partials + fused x->tf32 rounding.  grid = (T/64, KSPLIT), 256 thr.
// ---------------------------------------------------------------------------
__global__ __launch_bounds__(256) void gate_part(const float* __restrict__ x,
                                                 const float* __restrict__ gw,
                                                 float* __restrict__ lp,
                                                 float* __restrict__ xr)
{
    __shared__ float xs[64][68];
    __shared__ float gs[8][68];

    const int tid  = threadIdx.x;
    const int lane = tid & 31;
    const int warp = tid >> 5;
    const int tok0 = blockIdx.x * 64;
    const int kc0  = blockIdx.y * (DMODEL / KSPLIT);

    float acc[8][8];
#pragma unroll
    for (int i = 0; i < 8; i++)
#pragma unroll
        for (int e = 0; e < 8; e++) acc[i][e] = 0.f;

    const int lr = tid >> 4;
    const int lc = (tid & 15) * 4;

    for (int kc = kc0; kc < kc0 + DMODEL / KSPLIT; kc += 64) {
#pragma unroll
        for (int j = 0; j < 4; j++) {
            size_t gi = (size_t)(tok0 + lr + j * 16) * DMODEL + kc + lc;
            float4 v = *(const float4*)&x[gi];
            *(float4*)&xs[lr + j * 16][lc] = v;
            float4 r;
            r.x = __uint_as_float(f2tf(v.x));
            r.y = __uint_as_float(f2tf(v.y));
            r.z = __uint_as_float(f2tf(v.z));
            r.w = __uint_as_float(f2tf(v.w));
            *(float4*)&xr[gi] = r;
        }
        if (tid < 128) {
            int rr = tid >> 4;
            float4 v = *(const float4*)&gw[(size_t)rr * DMODEL + kc + lc];
            *(float4*)&gs[rr][lc] = v;
        }
        __syncthreads();

#pragma unroll
        for (int h = 0; h < 2; h++) {
            int kk = lane + h * 32;
            float gv[8];
#pragma unroll
            for (int e = 0; e < 8; e++) gv[e] = gs[e][kk];
#pragma unroll
            for (int i = 0; i < 8; i++) {
                float xv = xs[warp * 8 + i][kk];
#pragma unroll
                for (int e = 0; e < 8; e++) acc[i][e] += xv * gv[e];
            }
        }
        __syncthreads();
    }

#pragma unroll
    for (int off = 16; off > 0; off >>= 1)
#pragma unroll
        for (int i = 0; i < 8; i++)
#pragma unroll
            for (int e = 0; e < 8; e++)
                acc[i][e] += __shfl_xor_sync(0xffffffffu, acc[i][e], off);

#pragma unroll
    for (int i = 0; i < 8; i++) {
        if (lane == i) {
            int tok = tok0 + warp * 8 + i;
            size_t base = ((size_t)blockIdx.y * T_TOK + tok) * N_EXP;
#pragma unroll
            for (int e = 0; e < 8; e++) lp[base + e] = acc[i][e];
        }
    }
}

// ---------------------------------------------------------------------------
// Gate finalize + scatter into per-expert lists (atomic compaction).
// Row order is nondeterministic, but per-row values and the final 2-way
// commutative combine are order-independent -> output is stable.
// ---------------------------------------------------------------------------
__global__ __launch_bounds__(256) void gate_fin(const float* __restrict__ lp,
                                                int* __restrict__ cnt,
                                                int* __restrict__ list,
                                                float* __restrict__ wl)
{
    const int tok = blockIdx.x * 256 + threadIdx.x;
    float l[8];
#pragma unroll
    for (int e = 0; e < 8; e++) l[e] = 0.f;
#pragma unroll
    for (int s = 0; s < KSPLIT; s++) {
        size_t base = ((size_t)s * T_TOK + tok) * N_EXP;
#pragma unroll
        for (int e = 0; e < 8; e++) l[e] += lp[base + e];
    }
    float m1 = -1e30f; int e1 = 0;
#pragma unroll
    for (int e = 0; e < 8; e++)
        if (l[e] > m1) { m1 = l[e]; e1 = e; }
    float m2 = -1e30f; int e2 = 0;
#pragma unroll
    for (int e = 0; e < 8; e++)
        if (e != e1 && l[e] > m2) { m2 = l[e]; e2 = e; }
    float w1 = 1.0f / (1.0f + __expf(m2 - m1));

    int p1 = atomicAdd(&cnt[e1], 1);
    list[e1 * T_TOK + p1] = tok;
    wl[e1 * T_TOK + p1] = w1;
    int p2 = atomicAdd(&cnt[e2], 1);
    list[e2 * T_TOK + p2] = tok;
    wl[e2 * T_TOK + p2] = 1.0f - w1;
}

// ---------------------------------------------------------------------------
// GEMM1 sparse: H[e][i][r] = round( w_i * sum_k xr[tok_i,k] * Ar[e*64+r,k] )
// Block tile 128x64, BK=32, 2-stage cp.async. 128 thr, warps 2x2 (tile 64x32).
// grid.x = N_EXP*MAXTIL, early-exit beyond cnt[e].
// ---------------------------------------------------------------------------
#define G1_AT (128 * 36)
#define G1_BT (64 * 36)
#define G1_ST (G1_AT + G1_BT)
#define G1_DYN (2 * G1_ST * 4)

__global__ __launch_bounds__(128) void gemm1_sparse(const float* __restrict__ xr,
                                                    const float* __restrict__ Ar,
                                                    const int* __restrict__ cnt,
                                                    const int* __restrict__ list,
                                                    const float* __restrict__ wl,
                                                    float* __restrict__ H)
{
    const int e  = blockIdx.x >> 6;
    const int mt = blockIdx.x & (MAXTIL - 1);
    const int n  = cnt[e];
    if (mt * 128 >= n) return;

    __shared__ int   toks[128];
    __shared__ float ws[128];
    extern __shared__ float sm[];

    const int tid  = threadIdx.x;
    const int lane = tid & 31;
    const int warp = tid >> 5;
    const int wm   = warp >> 1;     // 0..1
    const int wn   = warp & 1;      // 0..1

    {
        int i = mt * 128 + tid;
        toks[tid] = list[e * T_TOK + i];          // pad entries: valid stale/0 index
        ws[tid]   = (i < n) ? wl[e * T_TOK + i] : 0.f;
    }
    __syncthreads();

    const uint32_t smbase = (uint32_t)__cvta_generic_to_shared(sm);
    const int lr4 = tid >> 3;          // 0..15
    const int lc4 = (tid & 7) * 4;     // 0..28

    // hoist gathered row pointers (fixed across k iterations)
    const float* ap[8];
#pragma unroll
    for (int j = 0; j < 8; j++)
        ap[j] = &xr[(size_t)toks[lr4 + j * 16] * DMODEL + lc4];
    const float* bp[4];
#pragma unroll
    for (int j = 0; j < 4; j++)
        bp[j] = &Ar[((size_t)e * 64 + lr4 + j * 16) * DMODEL + lc4];

    auto issue = [&](int kt) {
        const int s = kt & 1;
        const int k0 = kt * 32;
        const uint32_t sa = smbase + (uint32_t)(s * G1_ST) * 4u;
        const uint32_t sb = sa + G1_AT * 4u;
#pragma unroll
        for (int j = 0; j < 8; j++)
            cp_async16(sa + ((lr4 + j * 16) * 36 + lc4) * 4u, ap[j] + k0);
#pragma unroll
        for (int j = 0; j < 4; j++)
            cp_async16(sb + ((lr4 + j * 16) * 36 + lc4) * 4u, bp[j] + k0);
    };

    float c[4][4][4] = {};
    issue(0); cp_commit();

    const int r0 = lane >> 2;
    const int cq = lane & 3;
    constexpr int KT = DMODEL / 32;

    for (int kt = 0; kt < KT; kt++) {
        if (kt + 1 < KT) { issue(kt + 1); cp_commit(); cp_wait<1>(); }
        else             { cp_wait<0>(); }
        __syncthreads();

        const float* As = sm + (kt & 1) * G1_ST;
        const float* Bs = As + G1_AT;

#pragma unroll
        for (int kk = 0; kk < 4; kk++) {
            const int k8 = kk * 8;
            unsigned a[4][4], b[4][2];
#pragma unroll
            for (int mi = 0; mi < 4; mi++) {
                int rb = wm * 64 + mi * 16 + r0;
                a[mi][0] = __float_as_uint(As[rb * 36 + k8 + cq]);
                a[mi][1] = __float_as_uint(As[(rb + 8) * 36 + k8 + cq]);
                a[mi][2] = __float_as_uint(As[rb * 36 + k8 + cq + 4]);
                a[mi][3] = __float_as_uint(As[(rb + 8) * 36 + k8 + cq + 4]);
            }
#pragma unroll
            for (int ni = 0; ni < 4; ni++) {
                int nb = wn * 32 + ni * 8 + r0;
                b[ni][0] = __float_as_uint(Bs[nb * 36 + k8 + cq]);
                b[ni][1] = __float_as_uint(Bs[nb * 36 + k8 + cq + 4]);
            }
#pragma unroll
            for (int mi = 0; mi < 4; mi++)
#pragma unroll
                for (int ni = 0; ni < 4; ni++)
                    mma_tf32(c[mi][ni], a[mi], b[ni]);
        }
        __syncthreads();
    }

    // epilogue: fold routing weight, tf32-round, write compact H
#pragma unroll
    for (int mi = 0; mi < 4; mi++) {
#pragma unroll
        for (int ni = 0; ni < 4; ni++) {
            int row = wm * 64 + mi * 16 + r0;
            int col = wn * 32 + ni * 8 + cq * 2;
            float s0 = ws[row], s1 = ws[row + 8];
            float2 v0 = make_float2(__uint_as_float(f2tf(c[mi][ni][0] * s0)),
                                    __uint_as_float(f2tf(c[mi][ni][1] * s0)));
            float2 v1 = make_float2(__uint_as_float(f2tf(c[mi][ni][2] * s1)),
                                    __uint_as_float(f2tf(c[mi][ni][3] * s1)));
            size_t base = ((size_t)e * T_TOK + mt * 128);
            *(float2*)&H[(base + row) * RANK + col]     = v0;
            *(float2*)&H[(base + row + 8) * RANK + col] = v1;
        }
    }
}

// ---------------------------------------------------------------------------
// GEMM2 sparse: out[tok_i] += H[e][i] @ B_e^T.  Tile 128x128, K=64 one-shot.
// 256 thr, warps 2x4 (tile 64x32). grid = (32, N_EXP*MAXTIL). atomicAdd scatter.
// ---------------------------------------------------------------------------
#define G2_HT (128 * 68)
#define G2_DYN (2 * G2_HT * 4)

__global__ __launch_bounds__(256) void gemm2_sparse(const float* __restrict__ H,
                                                    const float* __restrict__ Br,
                                                    const int* __restrict__ cnt,
                                                    const int* __restrict__ list,
                                                    float* __restrict__ out)
{
    const int e  = blockIdx.y >> 6;
    const int mt = blockIdx.y & (MAXTIL - 1);
    const int n  = cnt[e];
    if (mt * 128 >= n) return;
    const int bn = blockIdx.x * 128;

    __shared__ int toks[128];
    extern __shared__ float sm[];
    float* Hs = sm;
    float* Bs = sm + G2_HT;

    const int tid  = threadIdx.x;
    const int lane = tid & 31;
    const int warp = tid >> 5;
    const int wm   = warp >> 2;   // 0..1
    const int wn   = warp & 3;    // 0..3

    if (tid < 128) toks[tid] = list[e * T_TOK + mt * 128 + tid];

    const uint32_t smbase = (uint32_t)__cvta_generic_to_shared(sm);
    const int lr4 = tid >> 4;          // 0..15
    const int lc4 = (tid & 15) * 4;    // 0..60

#pragma unroll
    for (int j = 0; j < 8; j++) {
        int row = lr4 + j * 16;
        cp_async16(smbase + (uint32_t)(row * 68 + lc4) * 4u,
                   &H[((size_t)e * T_TOK + mt * 128 + row) * RANK + lc4]);
        cp_async16(smbase + (uint32_t)(G2_HT + row * 68 + lc4) * 4u,
                   &Br[((size_t)e * DMODEL + bn + row) * RANK + lc4]);
    }
    cp_commit();
    cp_wait<0>();
    __syncthreads();

    float c[4][4][4] = {};
    const int r0 = lane >> 2;
    const int cq = lane & 3;

#pragma unroll
    for (int kk = 0; kk < 8; kk++) {
        const int k8 = kk * 8;
        unsigned a[4][4], b[4][2];
#pragma unroll
        for (int mi = 0; mi < 4; mi++) {
            int rb = wm * 64 + mi * 16 + r0;
            a[mi][0] = __float_as_uint(Hs[rb * 68 + k8 + cq]);
            a[mi][1] = __float_as_uint(Hs[(rb + 8) * 68 + k8 + cq]);
            a[mi][2] = __float_as_uint(Hs[rb * 68 + k8 + cq + 4]);
            a[mi][3] = __float_as_uint(Hs[(rb + 8) * 68 + k8 + cq + 4]);
        }
#pragma unroll
        for (int ni = 0; ni < 4; ni++) {
            int nb = wn * 32 + ni * 8 + r0;
            b[ni][0] = __float_as_uint(Bs[nb * 68 + k8 + cq]);
            b[ni][1] = __float_as_uint(Bs[nb * 68 + k8 + cq + 4]);
        }
#pragma unroll
        for (int mi = 0; mi < 4; mi++)
#pragma unroll
            for (int ni = 0; ni < 4; ni++)
                mma_tf32(c[mi][ni], a[mi], b[ni]);
    }

    // epilogue: guarded atomic scatter-add (exactly 2 contributions per out elem)
#pragma unroll
    for (int mi = 0; mi < 4; mi++) {
        int row = wm * 64 + mi * 16 + r0;
        bool v0 = (mt * 128 + row) < n;
        bool v1 = (mt * 128 + row + 8) < n;
        int t0 = toks[row];
        int t1 = toks[row + 8];
#pragma unroll
        for (int ni = 0; ni < 4; ni++) {
            int col = bn + wn * 32 + ni * 8 + cq * 2;
            if (v0) {
                atomicAdd(&out[(size_t)t0 * DMODEL + col],     c[mi][ni][0]);
                atomicAdd(&out[(size_t)t0 * DMODEL + col + 1], c[mi][ni][1]);
            }
            if (v1) {
                atomicAdd(&out[(size_t)t1 * DMODEL + col],     c[mi][ni][2]);
                atomicAdd(&out[(size_t)t1 * DMODEL + col + 1], c[mi][ni][3]);
            }
        }
    }
}

// ---------------------------------------------------------------------------
// launch
// ---------------------------------------------------------------------------
extern "C" void kernel_launch(void* const* d_in, const int* in_sizes, int n_in,
                              void* d_out, int out_size)
{
    const float* x  = (const float*)d_in[0];   // [4,2048,4096]
    const float* gw = (const float*)d_in[1];   // [8,4096]
    const float* lA = (const float*)d_in[2];   // [8,64,4096]
    const float* lB = (const float*)d_in[3];   // [8,4096,64]
    float* out = (float*)d_out;

    float *Hp, *lpp, *xr, *Ar, *Br, *wlp;
    int *cntp, *listp;
    cudaGetSymbolAddress((void**)&Hp,   g_H);
    cudaGetSymbolAddress((void**)&lpp,  g_lp);
    cudaGetSymbolAddress((void**)&xr,   g_xr);
    cudaGetSymbolAddress((void**)&Ar,   g_Ar);
    cudaGetSymbolAddress((void**)&Br,   g_Br);
    cudaGetSymbolAddress((void**)&cntp, g_cnt);
    cudaGetSymbolAddress((void**)&listp,g_list);
    cudaGetSymbolAddress((void**)&wlp,  g_wl);

    cudaFuncSetAttribute((const void*)gemm1_sparse,
                         cudaFuncAttributeMaxDynamicSharedMemorySize, G1_DYN);
    cudaFuncSetAttribute((const void*)gemm2_sparse,
                         cudaFuncAttributeMaxDynamicSharedMemorySize, G2_DYN);

    // 1) round LoRA weights to tf32
    round_tf32<<<(ER * DMODEL / 4 + 255) / 256, 256>>>((const float4*)lA, (float4*)Ar, ER * DMODEL / 4);
    round_tf32<<<(ER * DMODEL / 4 + 255) / 256, 256>>>((const float4*)lB, (float4*)Br, ER * DMODEL / 4);
    // 2) gate partials (fused x->tf32 rounding)
    gate_part<<<dim3(T_TOK / 64, KSPLIT), 256>>>(x, gw, lpp, xr);
    // 3) zero out + counters
    zero_out<<<(T_TOK * DMODEL / 4 + 255) / 256, 256>>>((float4*)out, T_TOK * DMODEL / 4, cntp);
    // 4) finalize gate + scatter tokens into expert lists
    gate_fin<<<T_TOK / 256, 256>>>(lpp, cntp, listp, wlp);
    // 5) sparse GEMM1: compact Hw per expert
    gemm1_sparse<<<N_EXP * MAXTIL, 128, G1_DYN>>>(xr, Ar, cntp, listp, wlp, Hp);
    // 6) sparse GEMM2: scatter-accumulate into out
    gemm2_sparse<<<dim3(DMODEL / 128, N_EXP * MAXTIL), 256, G2_DYN>>>(Hp, Br, cntp, listp, out);
}